// round 7
// baseline (speedup 1.0000x reference)
#include <cuda_runtime.h>
#include <cuda_bf16.h>
#include <cstdint>

// qpNet: z = max(-(x @ W^T + b), -1/EPS), EPS=1e-3  =>  z = max(-h, -1000)
// x: [B,5] f32, W: [5,5] f32, b: [5] f32, out: [B,5] f32. B = 4194304.
//
// R7: warp-granular decoupled bulk-TMA pipelines. Each warp owns a 2560B
// chunk (128 rows), private double-buffered in/out smem + 2 mbarriers.
// Lane 0 issues per-warp cp.async.bulk; NO __syncthreads in the main loop.

#define NEG_CLAMP    (-1000.0f)   // -1/EPS
#define CHUNK_FLOATS 640          // 128 rows * 5
#define CHUNK_BYTES  2560u
#define WARP_SMEM    10240        // in[2] + out[2], 4 * 2560
#define MBAR_OFF     81920        // 8 warps * 10240

extern __shared__ char smem_raw[];

__global__ void qp_kernel(
    const float* __restrict__ x,
    const float* __restrict__ W,
    const float* __restrict__ b,
    float* __restrict__ out,
    int nchunks)
{
    const int tid  = threadIdx.x;
    const int wid  = tid >> 5;
    const int lane = tid & 31;

    char* wbase = smem_raw + wid * WARP_SMEM;
    const unsigned in_s  = (unsigned)__cvta_generic_to_shared(wbase);
    const unsigned mb0   = (unsigned)__cvta_generic_to_shared(smem_raw + MBAR_OFF + wid * 16);

    if (lane == 0) {
        asm volatile("mbarrier.init.shared.b64 [%0], %1;" :: "r"(mb0),     "r"(1u));
        asm volatile("mbarrier.init.shared.b64 [%0], %1;" :: "r"(mb0 + 8), "r"(1u));
    }
    __syncwarp();   // warp-private barriers: only this warp ever touches them

    const long long wstride = (long long)gridDim.x * 8;
    const long long g0 = (long long)blockIdx.x * 8 + wid;

    // ---- prologue: prefetch chunks for iterations 0 and 1 ----
    if (lane == 0) {
        if (g0 < nchunks) {
            asm volatile("mbarrier.arrive.expect_tx.shared.b64 _, [%0], %1;"
                         :: "r"(mb0), "r"(CHUNK_BYTES) : "memory");
            asm volatile("cp.async.bulk.shared::cta.global.mbarrier::complete_tx::bytes "
                         "[%0], [%1], %2, [%3];"
                         :: "r"(in_s),
                            "l"((unsigned long long)(uintptr_t)(x + g0 * CHUNK_FLOATS)),
                            "r"(CHUNK_BYTES), "r"(mb0) : "memory");
        }
        if (g0 + wstride < nchunks) {
            asm volatile("mbarrier.arrive.expect_tx.shared.b64 _, [%0], %1;"
                         :: "r"(mb0 + 8), "r"(CHUNK_BYTES) : "memory");
            asm volatile("cp.async.bulk.shared::cta.global.mbarrier::complete_tx::bytes "
                         "[%0], [%1], %2, [%3];"
                         :: "r"(in_s + CHUNK_BYTES),
                            "l"((unsigned long long)(uintptr_t)(x + (g0 + wstride) * CHUNK_FLOATS)),
                            "r"(CHUNK_BYTES), "r"(mb0 + 8) : "memory");
        }
    }

    // ---- W [5,5] + b [5] while first loads are in flight ----
    float w[5][5], bb[5];
    {
        const float4* W4 = reinterpret_cast<const float4*>(W);
        float4 a0 = __ldg(W4 + 0);
        float4 a1 = __ldg(W4 + 1);
        float4 a2 = __ldg(W4 + 2);
        float4 a3 = __ldg(W4 + 3);
        float4 a4 = __ldg(W4 + 4);
        float4 a5 = __ldg(W4 + 5);
        float  a6 = __ldg(W + 24);
        w[0][0]=a0.x; w[0][1]=a0.y; w[0][2]=a0.z; w[0][3]=a0.w; w[0][4]=a1.x;
        w[1][0]=a1.y; w[1][1]=a1.z; w[1][2]=a1.w; w[1][3]=a2.x; w[1][4]=a2.y;
        w[2][0]=a2.z; w[2][1]=a2.w; w[2][2]=a3.x; w[2][3]=a3.y; w[2][4]=a3.z;
        w[3][0]=a3.w; w[3][1]=a4.x; w[3][2]=a4.y; w[3][3]=a4.z; w[3][4]=a4.w;
        w[4][0]=a5.x; w[4][1]=a5.y; w[4][2]=a5.z; w[4][3]=a5.w; w[4][4]=a6;
        const float4* b4 = reinterpret_cast<const float4*>(b);
        float4 bv = __ldg(b4);
        bb[0]=bv.x; bb[1]=bv.y; bb[2]=bv.z; bb[3]=bv.w; bb[4]=__ldg(b + 4);
    }

    for (long long g = g0, i = 0; g < nchunks; g += wstride, ++i) {
        const int      bsel = (int)(i & 1);
        const unsigned m    = mb0 + 8u * bsel;
        const int      ph   = (int)((i >> 1) & 1);
        float4* __restrict__ inbuf  = reinterpret_cast<float4*>(wbase + bsel * CHUNK_BYTES);
        float4* __restrict__ outbuf = reinterpret_cast<float4*>(wbase + 5120 + bsel * CHUNK_BYTES);

        // ---- wait for this chunk's TMA load (warp-only wait) ----
        asm volatile(
            "{\n\t"
            ".reg .pred P;\n\t"
            "WAIT_%=:\n\t"
            "mbarrier.try_wait.parity.acquire.cta.shared::cta.b64 P, [%0], %1, 0x989680;\n\t"
            "@P bra DONE_%=;\n\t"
            "bra WAIT_%=;\n\t"
            "DONE_%=:\n\t"
            "}"
            :: "r"(m), "r"(ph) : "memory");

        // ---- read own 4 rows: 5x LDS.128, conflict-free (80B stride) ----
        float4 v[5];
#pragma unroll
        for (int k = 0; k < 5; k++)
            v[k] = inbuf[5 * lane + k];

        // All lanes finished reading the in-buffer -> prefetch next chunk into it.
        __syncwarp();
        const long long gpre = g + 2 * wstride;
        if (lane == 0 && gpre < nchunks) {
            asm volatile("mbarrier.arrive.expect_tx.shared.b64 _, [%0], %1;"
                         :: "r"(m), "r"(CHUNK_BYTES) : "memory");
            asm volatile("cp.async.bulk.shared::cta.global.mbarrier::complete_tx::bytes "
                         "[%0], [%1], %2, [%3];"
                         :: "r"(in_s + (unsigned)bsel * CHUNK_BYTES),
                            "l"((unsigned long long)(uintptr_t)(x + gpre * CHUNK_FLOATS)),
                            "r"(CHUNK_BYTES), "r"(m) : "memory");
        }

        float xr[4][5];
        xr[0][0]=v[0].x; xr[0][1]=v[0].y; xr[0][2]=v[0].z; xr[0][3]=v[0].w; xr[0][4]=v[1].x;
        xr[1][0]=v[1].y; xr[1][1]=v[1].z; xr[1][2]=v[1].w; xr[1][3]=v[2].x; xr[1][4]=v[2].y;
        xr[2][0]=v[2].z; xr[2][1]=v[2].w; xr[2][2]=v[3].x; xr[2][3]=v[3].y; xr[2][4]=v[3].z;
        xr[3][0]=v[3].w; xr[3][1]=v[4].x; xr[3][2]=v[4].y; xr[3][3]=v[4].z; xr[3][4]=v[4].w;

        float zr[4][5];
#pragma unroll
        for (int r = 0; r < 4; r++) {
#pragma unroll
            for (int j = 0; j < 5; j++) {
                float h = bb[j];
#pragma unroll
                for (int k = 0; k < 5; k++)
                    h = fmaf(xr[r][k], w[j][k], h);
                zr[r][j] = fmaxf(-h, NEG_CLAMP);
            }
        }

        // Out-buffer reuse: the store issued from it 2 iterations ago must be
        // read-done. Lane 0 owns this warp's bulk group.
        if (lane == 0)
            asm volatile("cp.async.bulk.wait_group.read 1;" ::: "memory");
        __syncwarp();

#pragma unroll
        for (int k = 0; k < 5; k++)
            ;
        outbuf[5 * lane + 0] = make_float4(zr[0][0], zr[0][1], zr[0][2], zr[0][3]);
        outbuf[5 * lane + 1] = make_float4(zr[0][4], zr[1][0], zr[1][1], zr[1][2]);
        outbuf[5 * lane + 2] = make_float4(zr[1][3], zr[1][4], zr[2][0], zr[2][1]);
        outbuf[5 * lane + 3] = make_float4(zr[2][2], zr[2][3], zr[2][4], zr[3][0]);
        outbuf[5 * lane + 4] = make_float4(zr[3][1], zr[3][2], zr[3][3], zr[3][4]);

        __syncwarp();
        if (lane == 0) {
            asm volatile("fence.proxy.async.shared::cta;" ::: "memory");
            asm volatile("cp.async.bulk.global.shared::cta.bulk_group [%0], [%1], %2;"
                         :: "l"((unsigned long long)(uintptr_t)(out + g * CHUNK_FLOATS)),
                            "r"(in_s + 5120u + (unsigned)bsel * CHUNK_BYTES),
                            "r"(CHUNK_BYTES) : "memory");
            asm volatile("cp.async.bulk.commit_group;" ::: "memory");
        }
    }

    // Don't exit while bulk stores may still read this CTA's smem.
    if (lane == 0)
        asm volatile("cp.async.bulk.wait_group.read 0;" ::: "memory");
}

extern "C" void kernel_launch(void* const* d_in, const int* in_sizes, int n_in,
                              void* d_out, int out_size)
{
    const float* x = (const float*)d_in[0];   // [B,5]
    const float* W = (const float*)d_in[1];   // [5,5]
    const float* b = (const float*)d_in[2];   // [5]
    float* out = (float*)d_out;               // [B,5]

    const long long B = in_sizes[0] / 5;      // 4194304
    const int nchunks = (int)(B / 128);       // 32768 chunks of 2560 B, exact

    const int threads = 256;                  // 8 warps/CTA
    const int blocks  = 152 * 2;              // 2 CTAs/SM (smem-limited)
    const int smem    = MBAR_OFF + 8 * 16;    // 82048 B dynamic

    cudaFuncSetAttribute(qp_kernel, cudaFuncAttributeMaxDynamicSharedMemorySize, smem);
    qp_kernel<<<blocks, threads, smem>>>(x, W, b, out, nchunks);
}